// round 9
// baseline (speedup 1.0000x reference)
#include <cuda_runtime.h>
#include <cstdint>

#define IN_F   4096
#define OUT_F  4096
#define NTHREADS 128          // 4 warps -> 4 rows per block
#define ROWS_PER_BLOCK 4
#define NBLOCKS (OUT_F / ROWS_PER_BLOCK)   // 1024

__global__ __launch_bounds__(NTHREADS)
void unary_linear_kernel(
    const float* __restrict__ x,          // [1, IN_F]
    const float* __restrict__ buf_wght,   // [OUT_F, IN_F]
    const float* __restrict__ buf_bias,   // [OUT_F]
    const float* __restrict__ rng,        // [256] == bitrev8 table (computed in regs)
    const float* __restrict__ acc,        // [1, OUT_F]
    const float* __restrict__ acc_bound,  // [1]
    const int*   __restrict__ rng_wght_idx,     // [OUT_F, IN_F] int32
    const int*   __restrict__ rng_bias_idx,     // [OUT_F]
    const int*   __restrict__ rng_wght_idx_inv, // [OUT_F, IN_F]
    float*       __restrict__ out)        // [1, OUT_F]
{
    __shared__ uint32_t s_xb[IN_F / 32];  // 128 words: x packed to bits

    const int tid  = threadIdx.x;
    const int lane = tid & 31;
    const int wid  = tid >> 5;

    // ---- pack x into bitmask (one 16KB read of x per block) ----
    #pragma unroll
    for (int w0 = wid; w0 < IN_F / 32; w0 += NTHREADS / 32) {
        float xv = x[w0 * 32 + lane];
        uint32_t m = __ballot_sync(0xFFFFFFFFu, xv > 0.5f);
        if (lane == 0) s_xb[w0] = m;
    }
    __syncthreads();

    // ---- gather this lane's x-nibbles into 4 registers ----
    // iteration it (0..31): lane handles elements 128*it + 4*lane .. +3
    //   -> bit offset 4*lane + 128*it; word = 4*it + (lane>>3), shift = (lane&7)*4
    uint32_t xn[4];
    #pragma unroll
    for (int q = 0; q < 4; q++) {
        uint32_t acc_bits = 0;
        #pragma unroll
        for (int s = 0; s < 8; s++) {
            int it = 8 * q + s;
            uint32_t nib = (s_xb[4 * it + (lane >> 3)] >> ((lane & 7) * 4)) & 0xFu;
            acc_bits |= nib << (4 * s);
        }
        xn[q] = acc_bits;
    }

    // ---- each warp processes one full row ----
    const int j = blockIdx.x * ROWS_PER_BLOCK + wid;
    const size_t row = (size_t)j * IN_F;
    const float4* wrow = (const float4*)(buf_wght        + row);
    const int4*   iwr  = (const int4*)  (rng_wght_idx     + row);
    const int4*   ivr  = (const int4*)  (rng_wght_idx_inv + row);

    int sum = 0;
    // IN_F/4 = 1024 vec4; 32 lanes -> 32 iterations
    #pragma unroll 4
    for (int it = 0; it < IN_F / (4 * 32); it++) {
        int v = lane + 32 * it;
        float4 w  = __ldg(wrow + v);
        int4   ki = __ldg(iwr + v);
        int4   kv = __ldg(ivr + v);
        uint32_t nib = (xn[it >> 3] >> ((it & 7) * 4)) & 0xFu;

        // rng[k % 256] == (float)(__brev(k) >> 24)
        {
            uint32_t b = nib & 1u;
            uint32_t r = b ? (__brev((uint32_t)ki.x) >> 24) : (__brev((uint32_t)kv.x) >> 24);
            sum += ((w.x >= (float)r) == (b != 0));
        }
        {
            uint32_t b = (nib >> 1) & 1u;
            uint32_t r = b ? (__brev((uint32_t)ki.y) >> 24) : (__brev((uint32_t)kv.y) >> 24);
            sum += ((w.y >= (float)r) == (b != 0));
        }
        {
            uint32_t b = (nib >> 2) & 1u;
            uint32_t r = b ? (__brev((uint32_t)ki.z) >> 24) : (__brev((uint32_t)kv.z) >> 24);
            sum += ((w.z >= (float)r) == (b != 0));
        }
        {
            uint32_t b = (nib >> 3) & 1u;
            uint32_t r = b ? (__brev((uint32_t)ki.w) >> 24) : (__brev((uint32_t)kv.w) >> 24);
            sum += ((w.w >= (float)r) == (b != 0));
        }
    }

    // ---- warp reduce, lane 0 epilogue (no block sync needed) ----
    #pragma unroll
    for (int off = 16; off > 0; off >>= 1)
        sum += __shfl_down_sync(0xFFFFFFFFu, sum, off);

    if (lane == 0) {
        uint32_t kb = __brev((uint32_t)__ldg(rng_bias_idx + j)) >> 24;
        float b_bit = (__ldg(buf_bias + j) >= (float)kb) ? 1.0f : 0.0f;
        float acc_new = acc[j] + (float)sum + b_bit;
        out[j] = (acc_new >= acc_bound[0]) ? 1.0f : 0.0f;
    }
}

extern "C" void kernel_launch(void* const* d_in, const int* in_sizes, int n_in,
                              void* d_out, int out_size)
{
    const float* x            = (const float*)d_in[0];
    const float* buf_wght     = (const float*)d_in[1];
    const float* buf_bias     = (const float*)d_in[2];
    const float* rng          = (const float*)d_in[3];
    const float* acc          = (const float*)d_in[4];
    const float* acc_bound    = (const float*)d_in[5];
    const int*   rng_wght_idx     = (const int*)d_in[6];
    const int*   rng_bias_idx     = (const int*)d_in[7];
    const int*   rng_wght_idx_inv = (const int*)d_in[8];
    float* out = (float*)d_out;

    unary_linear_kernel<<<NBLOCKS, NTHREADS>>>(
        x, buf_wght, buf_bias, rng, acc, acc_bound,
        rng_wght_idx, rng_bias_idx, rng_wght_idx_inv, out);
}

// round 10
// speedup vs baseline: 1.0477x; 1.0477x over previous
#include <cuda_runtime.h>
#include <cstdint>

#define IN_F   4096
#define OUT_F  4096
#define NTHREADS 256

__device__ uint32_t g_xbits[IN_F / 32];   // 128 words, packed x bits

__global__ void pack_x_kernel(const float* __restrict__ x)
{
    const int lane = threadIdx.x & 31;
    const int wid  = threadIdx.x >> 5;
    #pragma unroll
    for (int w0 = wid; w0 < IN_F / 32; w0 += 4) {
        uint32_t m = __ballot_sync(0xFFFFFFFFu, x[w0 * 32 + lane] > 0.5f);
        if (lane == 0) g_xbits[w0] = m;
    }
}

__global__ __launch_bounds__(NTHREADS)
void unary_linear_kernel(
    const float* __restrict__ buf_wght,   // [OUT_F, IN_F]
    const float* __restrict__ buf_bias,   // [OUT_F]
    const float* __restrict__ acc,        // [1, OUT_F]
    const float* __restrict__ acc_bound,  // [1]
    const int*   __restrict__ rng_wght_idx,     // [OUT_F, IN_F] int32
    const int*   __restrict__ rng_bias_idx,     // [OUT_F]
    const int*   __restrict__ rng_wght_idx_inv, // [OUT_F, IN_F]
    float*       __restrict__ out)        // [1, OUT_F]
{
    __shared__ float s_red[NTHREADS / 32];

    const int tid  = threadIdx.x;
    const int lane = tid & 31;

    // x-bit words this thread needs: v = tid + 256*it, word = (tid>>3) + 32*it
    uint32_t xw[4];
    #pragma unroll
    for (int q = 0; q < 4; q++)
        xw[q] = __ldg(&g_xbits[(tid >> 3) + 32 * q]);
    const int xsh = (tid & 7) * 4;

    const int j = blockIdx.x;
    const size_t row = (size_t)j * IN_F;
    const float4* wrow = (const float4*)(buf_wght        + row);
    const int4*   iwr  = (const int4*)  (rng_wght_idx     + row);
    const int4*   ivr  = (const int4*)  (rng_wght_idx_inv + row);

    int sum = 0;
    // IN_F/4 = 1024 vec4, 256 threads -> 4 iterations
    #pragma unroll
    for (int it = 0; it < IN_F / (4 * NTHREADS); it++) {
        int v = tid + it * NTHREADS;
        float4 w  = __ldcs(wrow + v);   // streaming: read-once, evict-first
        int4   ki = __ldcs(iwr + v);
        int4   kv = __ldcs(ivr + v);
        uint32_t nib = (xw[it] >> xsh) & 0xFu;

        // rng[k % 256] == (float)(__brev(k) >> 24)  (8-bit van der Corput)
        {
            uint32_t b = nib & 1u;
            uint32_t r = b ? (__brev((uint32_t)ki.x) >> 24) : (__brev((uint32_t)kv.x) >> 24);
            sum += ((w.x >= (float)r) == (b != 0));
        }
        {
            uint32_t b = (nib >> 1) & 1u;
            uint32_t r = b ? (__brev((uint32_t)ki.y) >> 24) : (__brev((uint32_t)kv.y) >> 24);
            sum += ((w.y >= (float)r) == (b != 0));
        }
        {
            uint32_t b = (nib >> 2) & 1u;
            uint32_t r = b ? (__brev((uint32_t)ki.z) >> 24) : (__brev((uint32_t)kv.z) >> 24);
            sum += ((w.z >= (float)r) == (b != 0));
        }
        {
            uint32_t b = (nib >> 3) & 1u;
            uint32_t r = b ? (__brev((uint32_t)ki.w) >> 24) : (__brev((uint32_t)kv.w) >> 24);
            sum += ((w.w >= (float)r) == (b != 0));
        }
    }

    // warp reduce
    #pragma unroll
    for (int off = 16; off > 0; off >>= 1)
        sum += __shfl_down_sync(0xFFFFFFFFu, sum, off);

    if (lane == 0) s_red[tid >> 5] = (float)sum;
    __syncthreads();

    if (tid == 0) {
        float total = 0.0f;
        #pragma unroll
        for (int w = 0; w < NTHREADS / 32; w++) total += s_red[w];
        uint32_t kb = __brev((uint32_t)__ldg(rng_bias_idx + j)) >> 24;
        float b_bit = (__ldg(buf_bias + j) >= (float)kb) ? 1.0f : 0.0f;
        float acc_new = acc[j] + total + b_bit;
        out[j] = (acc_new >= acc_bound[0]) ? 1.0f : 0.0f;
    }
}

extern "C" void kernel_launch(void* const* d_in, const int* in_sizes, int n_in,
                              void* d_out, int out_size)
{
    const float* x            = (const float*)d_in[0];
    const float* buf_wght     = (const float*)d_in[1];
    const float* buf_bias     = (const float*)d_in[2];
    const float* acc          = (const float*)d_in[4];
    const float* acc_bound    = (const float*)d_in[5];
    const int*   rng_wght_idx     = (const int*)d_in[6];
    const int*   rng_bias_idx     = (const int*)d_in[7];
    const int*   rng_wght_idx_inv = (const int*)d_in[8];
    float* out = (float*)d_out;

    pack_x_kernel<<<1, 128>>>(x);
    unary_linear_kernel<<<OUT_F, NTHREADS>>>(
        buf_wght, buf_bias, acc, acc_bound,
        rng_wght_idx, rng_bias_idx, rng_wght_idx_inv, out);
}

// round 14
// speedup vs baseline: 1.1080x; 1.0576x over previous
#include <cuda_runtime.h>
#include <cstdint>

#define IN_F   4096
#define OUT_F  4096
#define NTHREADS 256

__global__ __launch_bounds__(NTHREADS, 8)
void unary_linear_kernel(
    const float* __restrict__ x,          // [1, IN_F] (L2-resident, 16 KB)
    const float* __restrict__ buf_wght,   // [OUT_F, IN_F]
    const float* __restrict__ buf_bias,   // [OUT_F]
    const float* __restrict__ acc,        // [1, OUT_F]
    const float* __restrict__ acc_bound,  // [1]
    const int*   __restrict__ rng_wght_idx,     // [OUT_F, IN_F] int32
    const int*   __restrict__ rng_bias_idx,     // [OUT_F]
    const int*   __restrict__ rng_wght_idx_inv, // [OUT_F, IN_F]
    float*       __restrict__ out)        // [1, OUT_F]
{
    __shared__ float s_red[NTHREADS / 32];

    const int tid  = threadIdx.x;
    const int lane = tid & 31;

    const int j = blockIdx.x;
    const size_t row = (size_t)j * IN_F;
    const float4* xv4  = (const float4*)x;
    const float4* wrow = (const float4*)(buf_wght        + row);
    const int4*   iwr  = (const int4*)  (rng_wght_idx     + row);
    const int4*   ivr  = (const int4*)  (rng_wght_idx_inv + row);

    int sum = 0;
    // IN_F/4 = 1024 vec4, 256 threads -> 4 iterations
    #pragma unroll
    for (int it = 0; it < IN_F / (4 * NTHREADS); it++) {
        int v = tid + it * NTHREADS;
        float4 xq = __ldg(xv4 + v);       // L2/L1 hit after first wave
        float4 w  = __ldcs(wrow + v);     // streaming, read-once
        int4   ki = __ldcs(iwr + v);
        int4   kv = __ldcs(ivr + v);

        // rng[k % 256] == (float)(__brev(k) >> 24)  (8-bit van der Corput)
        {
            bool b = xq.x > 0.5f;
            uint32_t r = b ? (__brev((uint32_t)ki.x) >> 24) : (__brev((uint32_t)kv.x) >> 24);
            sum += ((w.x >= (float)r) == b);
        }
        {
            bool b = xq.y > 0.5f;
            uint32_t r = b ? (__brev((uint32_t)ki.y) >> 24) : (__brev((uint32_t)kv.y) >> 24);
            sum += ((w.y >= (float)r) == b);
        }
        {
            bool b = xq.z > 0.5f;
            uint32_t r = b ? (__brev((uint32_t)ki.z) >> 24) : (__brev((uint32_t)kv.z) >> 24);
            sum += ((w.z >= (float)r) == b);
        }
        {
            bool b = xq.w > 0.5f;
            uint32_t r = b ? (__brev((uint32_t)ki.w) >> 24) : (__brev((uint32_t)kv.w) >> 24);
            sum += ((w.w >= (float)r) == b);
        }
    }

    // warp reduce
    #pragma unroll
    for (int off = 16; off > 0; off >>= 1)
        sum += __shfl_down_sync(0xFFFFFFFFu, sum, off);

    if (lane == 0) s_red[tid >> 5] = (float)sum;
    __syncthreads();

    if (tid == 0) {
        float total = 0.0f;
        #pragma unroll
        for (int w = 0; w < NTHREADS / 32; w++) total += s_red[w];
        uint32_t kb = __brev((uint32_t)__ldg(rng_bias_idx + j)) >> 24;
        float b_bit = (__ldg(buf_bias + j) >= (float)kb) ? 1.0f : 0.0f;
        float acc_new = acc[j] + total + b_bit;
        out[j] = (acc_new >= acc_bound[0]) ? 1.0f : 0.0f;
    }
}

extern "C" void kernel_launch(void* const* d_in, const int* in_sizes, int n_in,
                              void* d_out, int out_size)
{
    const float* x            = (const float*)d_in[0];
    const float* buf_wght     = (const float*)d_in[1];
    const float* buf_bias     = (const float*)d_in[2];
    const float* acc          = (const float*)d_in[4];
    const float* acc_bound    = (const float*)d_in[5];
    const int*   rng_wght_idx     = (const int*)d_in[6];
    const int*   rng_bias_idx     = (const int*)d_in[7];
    const int*   rng_wght_idx_inv = (const int*)d_in[8];
    float* out = (float*)d_out;

    unary_linear_kernel<<<OUT_F, NTHREADS>>>(
        x, buf_wght, buf_bias, acc, acc_bound,
        rng_wght_idx, rng_bias_idx, rng_wght_idx_inv, out);
}

// round 15
// speedup vs baseline: 1.1150x; 1.0063x over previous
#include <cuda_runtime.h>
#include <cstdint>

#define IN_F   4096
#define OUT_F  4096
#define NTHREADS 256
#define NBLOCKS  888   // ~6 CTAs/SM on 148 SMs, grid-stride over rows

__global__ __launch_bounds__(NTHREADS)
void unary_linear_kernel(
    const float* __restrict__ x,          // [1, IN_F]
    const float* __restrict__ buf_wght,   // [OUT_F, IN_F]
    const float* __restrict__ buf_bias,   // [OUT_F]
    const float* __restrict__ acc,        // [1, OUT_F]
    const float* __restrict__ acc_bound,  // [1]
    const int*   __restrict__ rng_wght_idx,     // [OUT_F, IN_F] int32
    const int*   __restrict__ rng_bias_idx,     // [OUT_F]
    const int*   __restrict__ rng_wght_idx_inv, // [OUT_F, IN_F]
    float*       __restrict__ out)        // [1, OUT_F]
{
    __shared__ float s_red[2][NTHREADS / 32];

    const int tid  = threadIdx.x;
    const int lane = tid & 31;
    const int wid  = tid >> 5;

    // ---- pack this thread's 16 x-bits once (elements 4v..4v+3, v=tid+256*it) ----
    const float4* xv4 = (const float4*)x;
    uint32_t xb = 0;
    #pragma unroll
    for (int q = 0; q < 4; q++) {
        float4 xq = __ldg(xv4 + tid + q * NTHREADS);
        xb |= (uint32_t)(xq.x > 0.5f) << (4 * q + 0);
        xb |= (uint32_t)(xq.y > 0.5f) << (4 * q + 1);
        xb |= (uint32_t)(xq.z > 0.5f) << (4 * q + 2);
        xb |= (uint32_t)(xq.w > 0.5f) << (4 * q + 3);
    }
    const float bound = __ldg(acc_bound);

    int buf = 0;
    for (int j = blockIdx.x; j < OUT_F; j += NBLOCKS, buf ^= 1) {
        const size_t row = (size_t)j * IN_F;
        const float4* wrow = (const float4*)(buf_wght        + row);
        const int4*   iwr  = (const int4*)  (rng_wght_idx     + row);
        const int4*   ivr  = (const int4*)  (rng_wght_idx_inv + row);

        int sum = 0;
        #pragma unroll
        for (int it = 0; it < IN_F / (4 * NTHREADS); it++) {
            int v = tid + it * NTHREADS;
            float4 w  = __ldcs(wrow + v);
            int4   ki = __ldcs(iwr + v);
            int4   kv = __ldcs(ivr + v);
            uint32_t nib = xb >> (4 * it);

            // rng[k % 256] == (float)(__brev(k) >> 24)  (8-bit van der Corput)
            {
                bool b = (nib & 1u) != 0;
                uint32_t r = b ? (__brev((uint32_t)ki.x) >> 24) : (__brev((uint32_t)kv.x) >> 24);
                sum += ((w.x >= (float)r) == b);
            }
            {
                bool b = (nib & 2u) != 0;
                uint32_t r = b ? (__brev((uint32_t)ki.y) >> 24) : (__brev((uint32_t)kv.y) >> 24);
                sum += ((w.y >= (float)r) == b);
            }
            {
                bool b = (nib & 4u) != 0;
                uint32_t r = b ? (__brev((uint32_t)ki.z) >> 24) : (__brev((uint32_t)kv.z) >> 24);
                sum += ((w.z >= (float)r) == b);
            }
            {
                bool b = (nib & 8u) != 0;
                uint32_t r = b ? (__brev((uint32_t)ki.w) >> 24) : (__brev((uint32_t)kv.w) >> 24);
                sum += ((w.w >= (float)r) == b);
            }
        }

        // warp reduce (redux.sync on sm_80+)
        sum = __reduce_add_sync(0xFFFFFFFFu, sum);
        if (lane == 0) s_red[buf][wid] = (float)sum;
        __syncthreads();

        if (tid == 0) {
            float total = 0.0f;
            #pragma unroll
            for (int w = 0; w < NTHREADS / 32; w++) total += s_red[buf][w];
            uint32_t kb = __brev((uint32_t)__ldg(rng_bias_idx + j)) >> 24;
            float b_bit = (__ldg(buf_bias + j) >= (float)kb) ? 1.0f : 0.0f;
            float acc_new = __ldg(acc + j) + total + b_bit;
            out[j] = (acc_new >= bound) ? 1.0f : 0.0f;
        }
        // no second sync: next iteration writes the other s_red buffer
    }
}

extern "C" void kernel_launch(void* const* d_in, const int* in_sizes, int n_in,
                              void* d_out, int out_size)
{
    const float* x            = (const float*)d_in[0];
    const float* buf_wght     = (const float*)d_in[1];
    const float* buf_bias     = (const float*)d_in[2];
    const float* acc          = (const float*)d_in[4];
    const float* acc_bound    = (const float*)d_in[5];
    const int*   rng_wght_idx     = (const int*)d_in[6];
    const int*   rng_bias_idx     = (const int*)d_in[7];
    const int*   rng_wght_idx_inv = (const int*)d_in[8];
    float* out = (float*)d_out;

    unary_linear_kernel<<<NBLOCKS, NTHREADS>>>(
        x, buf_wght, buf_bias, acc, acc_bound,
        rng_wght_idx, rng_bias_idx, rng_wght_idx_inv, out);
}

// round 16
// speedup vs baseline: 1.1757x; 1.0544x over previous
#include <cuda_runtime.h>
#include <cstdint>

#define IN_F   4096
#define OUT_F  4096
#define NTHREADS 256

__global__ __launch_bounds__(NTHREADS, 4)   // allow ~64 regs: front-batch 12 LDG.128
void unary_linear_kernel(
    const float* __restrict__ x,          // [1, IN_F]
    const float* __restrict__ buf_wght,   // [OUT_F, IN_F]
    const float* __restrict__ buf_bias,   // [OUT_F]
    const float* __restrict__ acc,        // [1, OUT_F]
    const float* __restrict__ acc_bound,  // [1]
    const int*   __restrict__ rng_wght_idx,     // [OUT_F, IN_F] int32
    const int*   __restrict__ rng_bias_idx,     // [OUT_F]
    const int*   __restrict__ rng_wght_idx_inv, // [OUT_F, IN_F]
    float*       __restrict__ out)        // [1, OUT_F]
{
    __shared__ float s_red[NTHREADS / 32];

    const int tid  = threadIdx.x;
    const int lane = tid & 31;

    // pack this thread's 16 x-bits into one register (x is L2-hot, 16 KB)
    const float4* xv4 = (const float4*)x;
    uint32_t xb = 0;
    #pragma unroll
    for (int q = 0; q < 4; q++) {
        float4 xq = __ldg(xv4 + tid + q * NTHREADS);
        xb |= (uint32_t)(xq.x > 0.5f) << (4 * q + 0);
        xb |= (uint32_t)(xq.y > 0.5f) << (4 * q + 1);
        xb |= (uint32_t)(xq.z > 0.5f) << (4 * q + 2);
        xb |= (uint32_t)(xq.w > 0.5f) << (4 * q + 3);
    }

    const int j = blockIdx.x;
    const size_t row = (size_t)j * IN_F;
    const float4* wrow = (const float4*)(buf_wght        + row);
    const int4*   iwr  = (const int4*)  (rng_wght_idx     + row);
    const int4*   ivr  = (const int4*)  (rng_wght_idx_inv + row);

    // ---- front-batch ALL loads for this row: 12 consecutive LDG.128 ----
    float4 w[4];
    int4   ki[4], kv[4];
    #pragma unroll
    for (int it = 0; it < 4; it++) w[it]  = __ldcs(wrow + tid + it * NTHREADS);
    #pragma unroll
    for (int it = 0; it < 4; it++) ki[it] = __ldcs(iwr  + tid + it * NTHREADS);
    #pragma unroll
    for (int it = 0; it < 4; it++) kv[it] = __ldcs(ivr  + tid + it * NTHREADS);

    // ---- compute ----
    int sum = 0;
    #pragma unroll
    for (int it = 0; it < 4; it++) {
        uint32_t nib = xb >> (4 * it);
        // rng[k % 256] == (float)(__brev(k) >> 24)  (8-bit van der Corput)
        {
            bool b = (nib & 1u) != 0;
            uint32_t r = b ? (__brev((uint32_t)ki[it].x) >> 24) : (__brev((uint32_t)kv[it].x) >> 24);
            sum += ((w[it].x >= (float)r) == b);
        }
        {
            bool b = (nib & 2u) != 0;
            uint32_t r = b ? (__brev((uint32_t)ki[it].y) >> 24) : (__brev((uint32_t)kv[it].y) >> 24);
            sum += ((w[it].y >= (float)r) == b);
        }
        {
            bool b = (nib & 4u) != 0;
            uint32_t r = b ? (__brev((uint32_t)ki[it].z) >> 24) : (__brev((uint32_t)kv[it].z) >> 24);
            sum += ((w[it].z >= (float)r) == b);
        }
        {
            bool b = (nib & 8u) != 0;
            uint32_t r = b ? (__brev((uint32_t)ki[it].w) >> 24) : (__brev((uint32_t)kv[it].w) >> 24);
            sum += ((w[it].w >= (float)r) == b);
        }
    }

    // warp reduce
    sum = __reduce_add_sync(0xFFFFFFFFu, sum);
    if (lane == 0) s_red[tid >> 5] = (float)sum;
    __syncthreads();

    if (tid == 0) {
        float total = 0.0f;
        #pragma unroll
        for (int w8 = 0; w8 < NTHREADS / 32; w8++) total += s_red[w8];
        uint32_t kb = __brev((uint32_t)__ldg(rng_bias_idx + j)) >> 24;
        float b_bit = (__ldg(buf_bias + j) >= (float)kb) ? 1.0f : 0.0f;
        float acc_new = __ldg(acc + j) + total + b_bit;
        out[j] = (acc_new >= __ldg(acc_bound)) ? 1.0f : 0.0f;
    }
}

extern "C" void kernel_launch(void* const* d_in, const int* in_sizes, int n_in,
                              void* d_out, int out_size)
{
    const float* x            = (const float*)d_in[0];
    const float* buf_wght     = (const float*)d_in[1];
    const float* buf_bias     = (const float*)d_in[2];
    const float* acc          = (const float*)d_in[4];
    const float* acc_bound    = (const float*)d_in[5];
    const int*   rng_wght_idx     = (const int*)d_in[6];
    const int*   rng_bias_idx     = (const int*)d_in[7];
    const int*   rng_wght_idx_inv = (const int*)d_in[8];
    float* out = (float*)d_out;

    unary_linear_kernel<<<OUT_F, NTHREADS>>>(
        x, buf_wght, buf_bias, acc, acc_bound,
        rng_wght_idx, rng_bias_idx, rng_wght_idx_inv, out);
}